// round 11
// baseline (speedup 1.0000x reference)
#include <cuda_runtime.h>
#include <cuda_fp16.h>
#include <cstdint>

#define N_NODES 50000
#define N_EDGES 800000
#define D_FEAT  128

// Scratch (device globals — no allocation allowed)
__device__ __half g_hh[N_NODES * D_FEAT];     // 12.8 MB, L2-resident
__device__ float g_s1[N_NODES];
__device__ float g_s2[N_NODES];
__device__ uint2 g_sd[N_EDGES];               // packed {src,dst}  6.4 MB
__device__ uint2 g_dw[N_EDGES];               // packed {dst,w}    6.4 MB
__device__ int   g_rowptr[N_NODES + 1];
__device__ int   g_edges64;                   // 1 if edges are int64, 0 if int32

// ---------------------------------------------------------------------------
// probe: detect edge dtype. int64 values < 2^31 have all-zero odd words.
// ---------------------------------------------------------------------------
__global__ void probe_kernel(const int* __restrict__ w) {
    __shared__ int any_nonzero;
    if (threadIdx.x == 0) any_nonzero = 0;
    __syncthreads();
    if (w[2 * threadIdx.x + 1] != 0) atomicExch(&any_nonzero, 1);
    __syncthreads();
    if (threadIdx.x == 0) g_edges64 = any_nonzero ? 0 : 1;
}

// ---------------------------------------------------------------------------
// prep: single pass over raw edges -> CSR rowptr + packed {src,dst}.
// After this, no kernel reads the int64 edge array again.
// ---------------------------------------------------------------------------
__global__ void prep_kernel(const int* __restrict__ ew) {
    const int is64 = g_edges64;
    const int stride = is64 ? 4 : 2;
    const int doff   = is64 ? 2 : 1;
    int e = blockIdx.x * blockDim.x + threadIdx.x;
    if (e >= N_EDGES) return;
    int s  = ew[e * stride];
    int d  = ew[e * stride + doff];
    g_sd[e] = make_uint2((unsigned)s, (unsigned)d);
    int sp = (e == 0) ? -1 : ew[(e - 1) * stride];
    for (int n = sp + 1; n <= s; ++n) g_rowptr[n] = e;
    if (e == N_EDGES - 1)
        for (int n = s + 1; n <= N_NODES; ++n) g_rowptr[n] = N_EDGES;
}

// ---------------------------------------------------------------------------
// GEMM: h = X @ W via tf32 mma.sync.m16n8k8 (tensor pipe), h stored as fp16.
// Fused epilogue: s1[row] = h[row]·ka[0:128], s2[row] = h[row]·ka[128:256].
// PTX ISA fragment layout for m16n8k8 tf32 (g=lane>>2, tig=lane&3):
//   a0=(g,tig) a1=(g+8,tig) a2=(g,tig+4) a3=(g+8,tig+4)
//   b0=(k=tig,n=g) b1=(k=tig+4,n=g)
//   c0=(g,2tig) c1=(g,2tig+1) c2=(g+8,2tig) c3=(g+8,2tig+1)
// ---------------------------------------------------------------------------
#define BM 128
#define BK 32
#define XS_STRIDE 40    // A 32-bit LDS: banks 8g+tig all distinct
#define WS_STRIDE 136   // B 32-bit LDS: banks 8tig+g all distinct

__device__ __forceinline__ uint32_t f2tf(float f) {
    uint32_t r;
    asm("cvt.rna.tf32.f32 %0, %1;" : "=r"(r) : "f"(f));
    return r;
}

__device__ __forceinline__ void mma_tf32(float c[4], uint32_t a0, uint32_t a1,
                                         uint32_t a2, uint32_t a3,
                                         uint32_t b0, uint32_t b1) {
    asm volatile(
        "mma.sync.aligned.m16n8k8.row.col.f32.tf32.tf32.f32 "
        "{%0,%1,%2,%3}, {%4,%5,%6,%7}, {%8,%9}, {%0,%1,%2,%3};\n"
        : "+f"(c[0]), "+f"(c[1]), "+f"(c[2]), "+f"(c[3])
        : "r"(a0), "r"(a1), "r"(a2), "r"(a3), "r"(b0), "r"(b1));
}

__global__ __launch_bounds__(256, 1) void gemm_kernel(const float* __restrict__ x,
                                                      const float* __restrict__ W,
                                                      const float* __restrict__ ka) {
    __shared__ uint32_t Xs[BM * XS_STRIDE];   // 20 KB
    __shared__ uint32_t Ws[BK * WS_STRIDE];   // 17 KB
    __shared__ float    sp1[4][BM];           // 2 KB
    __shared__ float    sp2[4][BM];           // 2 KB
    const int tid  = threadIdx.x;
    const int lane = tid & 31;
    const int warp = tid >> 5;
    const int wm = warp >> 2;
    const int wn = warp & 3;
    const int g   = lane >> 2;
    const int tig = lane & 3;
    const int row0 = blockIdx.x * BM;

    float c[4][4][4];
#pragma unroll
    for (int mt = 0; mt < 4; mt++)
#pragma unroll
        for (int nt = 0; nt < 4; nt++)
#pragma unroll
            for (int r = 0; r < 4; r++) c[mt][nt][r] = 0.f;

    for (int kc = 0; kc < 4; ++kc) {
#pragma unroll
        for (int i = 0; i < 4; i++) {
            int idx = tid + i * 256;
            int r = idx >> 3, c4 = (idx & 7) << 2;
            float4 v = make_float4(0.f, 0.f, 0.f, 0.f);
            if (row0 + r < N_NODES)
                v = *(const float4*)&x[(row0 + r) * D_FEAT + kc * BK + c4];
            uint32_t* p = &Xs[r * XS_STRIDE + c4];
            p[0] = f2tf(v.x); p[1] = f2tf(v.y); p[2] = f2tf(v.z); p[3] = f2tf(v.w);
        }
#pragma unroll
        for (int i = 0; i < 4; i++) {
            int idx = tid + i * 256;
            int r = idx >> 5, c4 = (idx & 31) << 2;
            float4 v = *(const float4*)&W[(kc * BK + r) * D_FEAT + c4];
            uint32_t* p = &Ws[r * WS_STRIDE + c4];
            p[0] = f2tf(v.x); p[1] = f2tf(v.y); p[2] = f2tf(v.z); p[3] = f2tf(v.w);
        }
        __syncthreads();

#pragma unroll
        for (int ks = 0; ks < 4; ++ks) {
            const int k0 = ks * 8;
            uint32_t b[4][2];
#pragma unroll
            for (int nt = 0; nt < 4; nt++) {
                int n = wn * 32 + nt * 8 + g;
                b[nt][0] = Ws[(k0 + tig) * WS_STRIDE + n];
                b[nt][1] = Ws[(k0 + tig + 4) * WS_STRIDE + n];
            }
#pragma unroll
            for (int mt = 0; mt < 4; mt++) {
                int rb = wm * 64 + mt * 16;
                uint32_t a0 = Xs[(rb + g) * XS_STRIDE + k0 + tig];
                uint32_t a1 = Xs[(rb + g + 8) * XS_STRIDE + k0 + tig];
                uint32_t a2 = Xs[(rb + g) * XS_STRIDE + k0 + tig + 4];
                uint32_t a3 = Xs[(rb + g + 8) * XS_STRIDE + k0 + tig + 4];
#pragma unroll
                for (int nt = 0; nt < 4; nt++)
                    mma_tf32(c[mt][nt], a0, a1, a2, a3, b[nt][0], b[nt][1]);
            }
        }
        __syncthreads();
    }

    float2 wa1f[4], wa2f[4];
#pragma unroll
    for (int nt = 0; nt < 4; nt++) {
        int col = wn * 32 + nt * 8 + 2 * tig;
        wa1f[nt] = *(const float2*)&ka[col];
        wa2f[nt] = *(const float2*)&ka[D_FEAT + col];
    }

#pragma unroll
    for (int mt = 0; mt < 4; mt++) {
        float p1a = 0.f, p2a = 0.f;
        float p1b = 0.f, p2b = 0.f;
#pragma unroll
        for (int nt = 0; nt < 4; nt++) {
            int r0 = row0 + wm * 64 + mt * 16 + g;
            int col = wn * 32 + nt * 8 + 2 * tig;
            if (r0 < N_NODES)
                *(__half2*)&g_hh[r0 * D_FEAT + col] =
                    __floats2half2_rn(c[mt][nt][0], c[mt][nt][1]);
            if (r0 + 8 < N_NODES)
                *(__half2*)&g_hh[(r0 + 8) * D_FEAT + col] =
                    __floats2half2_rn(c[mt][nt][2], c[mt][nt][3]);
            p1a += c[mt][nt][0] * wa1f[nt].x + c[mt][nt][1] * wa1f[nt].y;
            p2a += c[mt][nt][0] * wa2f[nt].x + c[mt][nt][1] * wa2f[nt].y;
            p1b += c[mt][nt][2] * wa1f[nt].x + c[mt][nt][3] * wa1f[nt].y;
            p2b += c[mt][nt][2] * wa2f[nt].x + c[mt][nt][3] * wa2f[nt].y;
        }
#pragma unroll
        for (int o = 1; o <= 2; o <<= 1) {
            p1a += __shfl_xor_sync(0xffffffffu, p1a, o);
            p2a += __shfl_xor_sync(0xffffffffu, p2a, o);
            p1b += __shfl_xor_sync(0xffffffffu, p1b, o);
            p2b += __shfl_xor_sync(0xffffffffu, p2b, o);
        }
        if (tig == 0) {
            int rl = wm * 64 + mt * 16 + g;
            sp1[wn][rl]     = p1a;  sp2[wn][rl]     = p2a;
            sp1[wn][rl + 8] = p1b;  sp2[wn][rl + 8] = p2b;
        }
    }
    __syncthreads();
    if (tid < BM) {
        int grow = row0 + tid;
        if (grow < N_NODES) {
            g_s1[grow] = sp1[0][tid] + sp1[1][tid] + sp1[2][tid] + sp1[3][tid];
            g_s2[grow] = sp2[0][tid] + sp2[1][tid] + sp2[2][tid] + sp2[3][tid];
        }
    }
}

// ---------------------------------------------------------------------------
// score: 2 edges per thread (independent chains for MLP). Reads packed
// {src,dst} (one uint4 = 2 edges), writes packed {dst, w} (one uint4).
// ---------------------------------------------------------------------------
__device__ __forceinline__ float edge_w(unsigned s, unsigned d) {
    float l = g_s1[s] + g_s2[d];
    l = (l > 0.f) ? l : 0.2f * l;          // leaky_relu(0.2)
    l = fminf(fmaxf(l, -2.f), 2.f);        // clip
    return __expf(l);
}

__global__ void score_kernel() {
    int t = blockIdx.x * blockDim.x + threadIdx.x;
    int e = t * 2;
    if (e >= N_EDGES) return;
    uint4 sd2 = *(const uint4*)&g_sd[e];   // {s0,d0,s1,d1}
    float w0 = edge_w(sd2.x, sd2.y);
    float w1 = edge_w(sd2.z, sd2.w);
    uint4 out;
    out.x = sd2.y; out.y = __float_as_uint(w0);
    out.z = sd2.w; out.w = __float_as_uint(w1);
    *(uint4*)&g_dw[e] = out;
}

// ---------------------------------------------------------------------------
// agg: TWO nodes per warp, 16 lanes each; lane owns 8 cols (one uint4 row
// slice). Inner loop: one uint4 load = 2 edges of {dst,w}, then gathers+FMA.
// Odd-start peeling keeps uint4 loads 16B-aligned. Unroll: 4 edges/iter.
// ---------------------------------------------------------------------------
__device__ __forceinline__ void acc8(float4& a, float4& b, float w, uint4 r) {
    float2 f0 = __half22float2(*(__half2*)&r.x);
    float2 f1 = __half22float2(*(__half2*)&r.y);
    float2 f2 = __half22float2(*(__half2*)&r.z);
    float2 f3 = __half22float2(*(__half2*)&r.w);
    a.x += w * f0.x; a.y += w * f0.y; a.z += w * f1.x; a.w += w * f1.y;
    b.x += w * f2.x; b.y += w * f2.y; b.z += w * f3.x; b.w += w * f3.y;
}

__global__ void agg_kernel(float* __restrict__ out) {
    int t = blockIdx.x * blockDim.x + threadIdx.x;
    int warp = t >> 5, lane = t & 31;
    int hl = lane & 15;
    int node = (warp << 1) | (lane >> 4);
    if (node >= N_NODES) return;
    const int e0 = g_rowptr[node];
    const int e1 = g_rowptr[node + 1];
    const __half* __restrict__ hc = g_hh + hl * 8;

    float4 accA = make_float4(0.f, 0.f, 0.f, 0.f);
    float4 accB = make_float4(0.f, 0.f, 0.f, 0.f);
    float denom = 0.f;
    int e = e0;
    if ((e & 1) && e < e1) {               // align to even edge
        uint2 q = g_dw[e];
        float w = __uint_as_float(q.y);
        uint4 r = *(const uint4*)&hc[q.x * D_FEAT];
        denom += w;
        acc8(accA, accB, w, r);
        ++e;
    }
    for (; e + 4 <= e1; e += 4) {
        uint4 p0 = *(const uint4*)&g_dw[e];      // edges e, e+1
        uint4 p1 = *(const uint4*)&g_dw[e + 2];  // edges e+2, e+3
        float w0 = __uint_as_float(p0.y);
        float w1 = __uint_as_float(p0.w);
        float w2 = __uint_as_float(p1.y);
        float w3 = __uint_as_float(p1.w);
        uint4 r0 = *(const uint4*)&hc[p0.x * D_FEAT];
        uint4 r1 = *(const uint4*)&hc[p0.z * D_FEAT];
        uint4 r2 = *(const uint4*)&hc[p1.x * D_FEAT];
        uint4 r3 = *(const uint4*)&hc[p1.z * D_FEAT];
        denom += (w0 + w1) + (w2 + w3);
        acc8(accA, accB, w0, r0);
        acc8(accA, accB, w1, r1);
        acc8(accA, accB, w2, r2);
        acc8(accA, accB, w3, r3);
    }
    for (; e + 2 <= e1; e += 2) {
        uint4 p0 = *(const uint4*)&g_dw[e];
        float w0 = __uint_as_float(p0.y);
        float w1 = __uint_as_float(p0.w);
        uint4 r0 = *(const uint4*)&hc[p0.x * D_FEAT];
        uint4 r1 = *(const uint4*)&hc[p0.z * D_FEAT];
        denom += w0 + w1;
        acc8(accA, accB, w0, r0);
        acc8(accA, accB, w1, r1);
    }
    if (e < e1) {
        uint2 q = g_dw[e];
        float w = __uint_as_float(q.y);
        uint4 r = *(const uint4*)&hc[q.x * D_FEAT];
        denom += w;
        acc8(accA, accB, w, r);
    }
    float rinv = (e1 > e0) ? (1.0f / denom) : 0.f;
    accA.x *= rinv; accA.y *= rinv; accA.z *= rinv; accA.w *= rinv;
    accB.x *= rinv; accB.y *= rinv; accB.z *= rinv; accB.w *= rinv;
    float* o = out + node * D_FEAT + hl * 8;
    *(float4*)o       = accA;
    *(float4*)(o + 4) = accB;
}

// ---------------------------------------------------------------------------
extern "C" void kernel_launch(void* const* d_in, const int* in_sizes, int n_in,
                              void* d_out, int out_size) {
    // Identify inputs by element count (ordering-proof).
    const float* x  = nullptr;   // node_states: 6,400,000
    const void*  ed = nullptr;   // edges:       1,600,000
    const float* W  = nullptr;   // kernel:         16,384
    const float* ka = nullptr;   // kernel_attention:  256
    for (int i = 0; i < n_in; i++) {
        switch (in_sizes[i]) {
            case 6400000: x  = (const float*)d_in[i]; break;
            case 1600000: ed = d_in[i];               break;
            case 16384:   W  = (const float*)d_in[i]; break;
            case 256:     ka = (const float*)d_in[i]; break;
            default: break;
        }
    }
    float* out = (float*)d_out;  // [50000,128] float32

    probe_kernel<<<1, 1024>>>((const int*)ed);
    prep_kernel<<<(N_EDGES + 255) / 256, 256>>>((const int*)ed);
    gemm_kernel<<<(N_NODES + BM - 1) / BM, 256>>>(x, W, ka);
    score_kernel<<<(N_EDGES / 2 + 255) / 256, 256>>>();
    agg_kernel<<<(N_NODES * 16 + 255) / 256, 256>>>(out);
}

// round 13
// speedup vs baseline: 1.0950x; 1.0950x over previous
#include <cuda_runtime.h>
#include <cuda_fp16.h>
#include <cstdint>

#define N_NODES 50000
#define N_EDGES 800000
#define D_FEAT  128

// Scratch (device globals — no allocation allowed)
__device__ __half g_hh[N_NODES * D_FEAT];     // 12.8 MB, L2-resident
__device__ float g_s1[N_NODES];
__device__ float g_s2[N_NODES];
__device__ int   g_dst[N_EDGES];              // compact dst  3.2 MB
__device__ float g_w[N_EDGES];                // edge scores  3.2 MB
__device__ int   g_rowptr[N_NODES + 1];

// ---------------------------------------------------------------------------
// GEMM: h = X @ W via tf32 mma.sync.m16n8k8 (tensor pipe), h stored as fp16.
// Fused epilogue: s1[row] = h[row]·ka[0:128], s2[row] = h[row]·ka[128:256].
// PTX ISA fragment layout for m16n8k8 tf32 (g=lane>>2, tig=lane&3):
//   a0=(g,tig) a1=(g+8,tig) a2=(g,tig+4) a3=(g+8,tig+4)
//   b0=(k=tig,n=g) b1=(k=tig+4,n=g)
//   c0=(g,2tig) c1=(g,2tig+1) c2=(g+8,2tig) c3=(g+8,2tig+1)
// ---------------------------------------------------------------------------
#define BM 128
#define BK 32
#define XS_STRIDE 40    // A 32-bit LDS: banks 8g+tig all distinct
#define WS_STRIDE 136   // B 32-bit LDS: banks 8tig+g all distinct

__device__ __forceinline__ uint32_t f2tf(float f) {
    uint32_t r;
    asm("cvt.rna.tf32.f32 %0, %1;" : "=r"(r) : "f"(f));
    return r;
}

__device__ __forceinline__ void mma_tf32(float c[4], uint32_t a0, uint32_t a1,
                                         uint32_t a2, uint32_t a3,
                                         uint32_t b0, uint32_t b1) {
    asm volatile(
        "mma.sync.aligned.m16n8k8.row.col.f32.tf32.tf32.f32 "
        "{%0,%1,%2,%3}, {%4,%5,%6,%7}, {%8,%9}, {%0,%1,%2,%3};\n"
        : "+f"(c[0]), "+f"(c[1]), "+f"(c[2]), "+f"(c[3])
        : "r"(a0), "r"(a1), "r"(a2), "r"(a3), "r"(b0), "r"(b1));
}

__global__ __launch_bounds__(256, 1) void gemm_kernel(const float* __restrict__ x,
                                                      const float* __restrict__ W,
                                                      const float* __restrict__ ka) {
    __shared__ uint32_t Xs[BM * XS_STRIDE];   // 20 KB
    __shared__ uint32_t Ws[BK * WS_STRIDE];   // 17 KB
    __shared__ float    sp1[4][BM];           // 2 KB
    __shared__ float    sp2[4][BM];           // 2 KB
    const int tid  = threadIdx.x;
    const int lane = tid & 31;
    const int warp = tid >> 5;
    const int wm = warp >> 2;
    const int wn = warp & 3;
    const int g   = lane >> 2;
    const int tig = lane & 3;
    const int row0 = blockIdx.x * BM;

    float c[4][4][4];
#pragma unroll
    for (int mt = 0; mt < 4; mt++)
#pragma unroll
        for (int nt = 0; nt < 4; nt++)
#pragma unroll
            for (int r = 0; r < 4; r++) c[mt][nt][r] = 0.f;

    for (int kc = 0; kc < 4; ++kc) {
#pragma unroll
        for (int i = 0; i < 4; i++) {
            int idx = tid + i * 256;
            int r = idx >> 3, c4 = (idx & 7) << 2;
            float4 v = make_float4(0.f, 0.f, 0.f, 0.f);
            if (row0 + r < N_NODES)
                v = *(const float4*)&x[(row0 + r) * D_FEAT + kc * BK + c4];
            uint32_t* p = &Xs[r * XS_STRIDE + c4];
            p[0] = f2tf(v.x); p[1] = f2tf(v.y); p[2] = f2tf(v.z); p[3] = f2tf(v.w);
        }
#pragma unroll
        for (int i = 0; i < 4; i++) {
            int idx = tid + i * 256;
            int r = idx >> 5, c4 = (idx & 31) << 2;
            float4 v = *(const float4*)&W[(kc * BK + r) * D_FEAT + c4];
            uint32_t* p = &Ws[r * WS_STRIDE + c4];
            p[0] = f2tf(v.x); p[1] = f2tf(v.y); p[2] = f2tf(v.z); p[3] = f2tf(v.w);
        }
        __syncthreads();

#pragma unroll
        for (int ks = 0; ks < 4; ++ks) {
            const int k0 = ks * 8;
            uint32_t b[4][2];
#pragma unroll
            for (int nt = 0; nt < 4; nt++) {
                int n = wn * 32 + nt * 8 + g;
                b[nt][0] = Ws[(k0 + tig) * WS_STRIDE + n];
                b[nt][1] = Ws[(k0 + tig + 4) * WS_STRIDE + n];
            }
#pragma unroll
            for (int mt = 0; mt < 4; mt++) {
                int rb = wm * 64 + mt * 16;
                uint32_t a0 = Xs[(rb + g) * XS_STRIDE + k0 + tig];
                uint32_t a1 = Xs[(rb + g + 8) * XS_STRIDE + k0 + tig];
                uint32_t a2 = Xs[(rb + g) * XS_STRIDE + k0 + tig + 4];
                uint32_t a3 = Xs[(rb + g + 8) * XS_STRIDE + k0 + tig + 4];
#pragma unroll
                for (int nt = 0; nt < 4; nt++)
                    mma_tf32(c[mt][nt], a0, a1, a2, a3, b[nt][0], b[nt][1]);
            }
        }
        __syncthreads();
    }

    float2 wa1f[4], wa2f[4];
#pragma unroll
    for (int nt = 0; nt < 4; nt++) {
        int col = wn * 32 + nt * 8 + 2 * tig;
        wa1f[nt] = *(const float2*)&ka[col];
        wa2f[nt] = *(const float2*)&ka[D_FEAT + col];
    }

#pragma unroll
    for (int mt = 0; mt < 4; mt++) {
        float p1a = 0.f, p2a = 0.f;
        float p1b = 0.f, p2b = 0.f;
#pragma unroll
        for (int nt = 0; nt < 4; nt++) {
            int r0 = row0 + wm * 64 + mt * 16 + g;
            int col = wn * 32 + nt * 8 + 2 * tig;
            if (r0 < N_NODES)
                *(__half2*)&g_hh[r0 * D_FEAT + col] =
                    __floats2half2_rn(c[mt][nt][0], c[mt][nt][1]);
            if (r0 + 8 < N_NODES)
                *(__half2*)&g_hh[(r0 + 8) * D_FEAT + col] =
                    __floats2half2_rn(c[mt][nt][2], c[mt][nt][3]);
            p1a += c[mt][nt][0] * wa1f[nt].x + c[mt][nt][1] * wa1f[nt].y;
            p2a += c[mt][nt][0] * wa2f[nt].x + c[mt][nt][1] * wa2f[nt].y;
            p1b += c[mt][nt][2] * wa1f[nt].x + c[mt][nt][3] * wa1f[nt].y;
            p2b += c[mt][nt][2] * wa2f[nt].x + c[mt][nt][3] * wa2f[nt].y;
        }
#pragma unroll
        for (int o = 1; o <= 2; o <<= 1) {
            p1a += __shfl_xor_sync(0xffffffffu, p1a, o);
            p2a += __shfl_xor_sync(0xffffffffu, p2a, o);
            p1b += __shfl_xor_sync(0xffffffffu, p1b, o);
            p2b += __shfl_xor_sync(0xffffffffu, p2b, o);
        }
        if (tig == 0) {
            int rl = wm * 64 + mt * 16 + g;
            sp1[wn][rl]     = p1a;  sp2[wn][rl]     = p2a;
            sp1[wn][rl + 8] = p1b;  sp2[wn][rl + 8] = p2b;
        }
    }
    __syncthreads();
    if (tid < BM) {
        int grow = row0 + tid;
        if (grow < N_NODES) {
            g_s1[grow] = sp1[0][tid] + sp1[1][tid] + sp1[2][tid] + sp1[3][tid];
            g_s2[grow] = sp2[0][tid] + sp2[1][tid] + sp2[2][tid] + sp2[3][tid];
        }
    }
}

// ---------------------------------------------------------------------------
// edge: ONE pass over raw edges -> rowptr + compact dst + scores.
// Per-block inline dtype probe (first 512 odd words; L2-broadcast after blk 0).
// int64 edge values < 2^31 have all-zero odd 32-bit words; int32 layout puts
// random dst ids there (P(512 consecutive zeros) ~ 0).
// ---------------------------------------------------------------------------
__global__ void edge_kernel(const int* __restrict__ ew) {
    __shared__ int nz;
    if (threadIdx.x == 0) nz = 0;
    __syncthreads();
    for (int i = threadIdx.x; i < 512; i += blockDim.x)
        if (ew[2 * i + 1] != 0) nz = 1;   // benign race, same value
    __syncthreads();
    const int stride = nz ? 2 : 4;        // nz -> int32 ; all-zero -> int64
    const int doff   = nz ? 1 : 2;

    int e = blockIdx.x * blockDim.x + threadIdx.x;
    if (e >= N_EDGES) return;
    int s = ew[e * stride];
    int d = ew[e * stride + doff];
    g_dst[e] = d;

    float l = g_s1[s] + g_s2[d];
    l = (l > 0.f) ? l : 0.2f * l;          // leaky_relu(0.2)
    l = fminf(fmaxf(l, -2.f), 2.f);        // clip
    g_w[e] = __expf(l);

    int sp = (e == 0) ? -1 : ew[(e - 1) * stride];
    for (int n = sp + 1; n <= s; ++n) g_rowptr[n] = e;
    if (e == N_EDGES - 1)
        for (int n = s + 1; n <= N_NODES; ++n) g_rowptr[n] = N_EDGES;
}

// ---------------------------------------------------------------------------
// agg: TWO nodes per warp, 16 lanes each; lane owns 8 cols (one uint4 row
// slice). Scores precomputed; dst compact. Unroll-4 for MLP against L2.
// ---------------------------------------------------------------------------
__device__ __forceinline__ void acc8(float4& a, float4& b, float w, uint4 r) {
    float2 f0 = __half22float2(*(__half2*)&r.x);
    float2 f1 = __half22float2(*(__half2*)&r.y);
    float2 f2 = __half22float2(*(__half2*)&r.z);
    float2 f3 = __half22float2(*(__half2*)&r.w);
    a.x += w * f0.x; a.y += w * f0.y; a.z += w * f1.x; a.w += w * f1.y;
    b.x += w * f2.x; b.y += w * f2.y; b.z += w * f3.x; b.w += w * f3.y;
}

__global__ void agg_kernel(float* __restrict__ out) {
    int t = blockIdx.x * blockDim.x + threadIdx.x;
    int warp = t >> 5, lane = t & 31;
    int hl = lane & 15;
    int node = (warp << 1) | (lane >> 4);
    if (node >= N_NODES) return;
    const int e0 = g_rowptr[node];
    const int e1 = g_rowptr[node + 1];
    const __half* __restrict__ hc = g_hh + hl * 8;

    float4 accA = make_float4(0.f, 0.f, 0.f, 0.f);
    float4 accB = make_float4(0.f, 0.f, 0.f, 0.f);
    float denom = 0.f;
    int e = e0;
    for (; e + 4 <= e1; e += 4) {
        int d0 = g_dst[e];
        int d1 = g_dst[e + 1];
        int d2 = g_dst[e + 2];
        int d3 = g_dst[e + 3];
        float w0 = g_w[e];
        float w1 = g_w[e + 1];
        float w2 = g_w[e + 2];
        float w3 = g_w[e + 3];
        uint4 r0 = *(const uint4*)&hc[d0 * D_FEAT];
        uint4 r1 = *(const uint4*)&hc[d1 * D_FEAT];
        uint4 r2 = *(const uint4*)&hc[d2 * D_FEAT];
        uint4 r3 = *(const uint4*)&hc[d3 * D_FEAT];
        denom += (w0 + w1) + (w2 + w3);
        acc8(accA, accB, w0, r0);
        acc8(accA, accB, w1, r1);
        acc8(accA, accB, w2, r2);
        acc8(accA, accB, w3, r3);
    }
    for (; e < e1; ++e) {
        int d = g_dst[e];
        float w = g_w[e];
        uint4 r = *(const uint4*)&hc[d * D_FEAT];
        denom += w;
        acc8(accA, accB, w, r);
    }
    float rinv = (e1 > e0) ? (1.0f / denom) : 0.f;
    accA.x *= rinv; accA.y *= rinv; accA.z *= rinv; accA.w *= rinv;
    accB.x *= rinv; accB.y *= rinv; accB.z *= rinv; accB.w *= rinv;
    float* o = out + node * D_FEAT + hl * 8;
    *(float4*)o       = accA;
    *(float4*)(o + 4) = accB;
}

// ---------------------------------------------------------------------------
extern "C" void kernel_launch(void* const* d_in, const int* in_sizes, int n_in,
                              void* d_out, int out_size) {
    // Identify inputs by element count (ordering-proof).
    const float* x  = nullptr;   // node_states: 6,400,000
    const void*  ed = nullptr;   // edges:       1,600,000
    const float* W  = nullptr;   // kernel:         16,384
    const float* ka = nullptr;   // kernel_attention:  256
    for (int i = 0; i < n_in; i++) {
        switch (in_sizes[i]) {
            case 6400000: x  = (const float*)d_in[i]; break;
            case 1600000: ed = d_in[i];               break;
            case 16384:   W  = (const float*)d_in[i]; break;
            case 256:     ka = (const float*)d_in[i]; break;
            default: break;
        }
    }
    float* out = (float*)d_out;  // [50000,128] float32

    gemm_kernel<<<(N_NODES + BM - 1) / BM, 256>>>(x, W, ka);
    edge_kernel<<<(N_EDGES + 255) / 256, 256>>>((const int*)ed);
    agg_kernel<<<(N_NODES * 16 + 255) / 256, 256>>>(out);
}

// round 15
// speedup vs baseline: 1.2100x; 1.1050x over previous
#include <cuda_runtime.h>
#include <cuda_fp16.h>
#include <cstdint>

#define N_NODES 50000
#define N_EDGES 800000
#define D_FEAT  128

// Scratch (device globals — no allocation allowed)
__device__ __half g_hh[N_NODES * D_FEAT];     // 12.8 MB, L2-resident
__device__ float g_s1[N_NODES];
__device__ float g_s2[N_NODES];
__device__ int   g_dst[N_EDGES];              // compact dst  3.2 MB
__device__ float g_w[N_EDGES];                // edge scores  3.2 MB
__device__ int   g_rowptr[N_NODES + 1];

// ---------------------------------------------------------------------------
// GEMM: h = X @ W via tf32 mma.sync.m16n8k8, cp.async double-buffered.
// Smem holds raw fp32; cvt.rna.tf32 applied at fragment-load time (same
// rounding as before -> identical numerics). Fused epilogue computes
// s1[row]=h·ka[0:128], s2[row]=h·ka[128:256] from fp32 accumulators.
// PTX ISA fragment layout m16n8k8 tf32 (g=lane>>2, tig=lane&3):
//   a0=(g,tig) a1=(g+8,tig) a2=(g,tig+4) a3=(g+8,tig+4)
//   b0=(k=tig,n=g) b1=(k=tig+4,n=g)
//   c0=(g,2tig) c1=(g,2tig+1) c2=(g+8,2tig) c3=(g+8,2tig+1)
// ---------------------------------------------------------------------------
#define BM 128
#define BK 32
#define XS_STRIDE 40    // A 32-bit LDS: banks 8g+tig all distinct
#define WS_STRIDE 136   // B 32-bit LDS: banks 8tig+g all distinct

// dynamic smem layout (floats)
#define XBUF_WORDS (BM * XS_STRIDE)           // 5120
#define WBUF_WORDS (BK * WS_STRIDE)           // 4352
#define OFF_X0 0
#define OFF_X1 (OFF_X0 + XBUF_WORDS)
#define OFF_W0 (OFF_X1 + XBUF_WORDS)
#define OFF_W1 (OFF_W0 + WBUF_WORDS)
#define OFF_SP1 (OFF_W1 + WBUF_WORDS)         // 4*BM
#define OFF_SP2 (OFF_SP1 + 4 * BM)
#define SMEM_WORDS (OFF_SP2 + 4 * BM)         // 19968
#define SMEM_BYTES (SMEM_WORDS * 4)           // 79872

__device__ __forceinline__ uint32_t f2tf(float f) {
    uint32_t r;
    asm("cvt.rna.tf32.f32 %0, %1;" : "=r"(r) : "f"(f));
    return r;
}

__device__ __forceinline__ void cp16(float* dst_smem, const float* src, bool valid) {
    uint32_t d = (uint32_t)__cvta_generic_to_shared(dst_smem);
    int sz = valid ? 16 : 0;
    asm volatile("cp.async.cg.shared.global [%0], [%1], 16, %2;\n"
                 :: "r"(d), "l"(src), "r"(sz));
}
__device__ __forceinline__ void cp_commit() {
    asm volatile("cp.async.commit_group;\n");
}
template <int N>
__device__ __forceinline__ void cp_wait() {
    asm volatile("cp.async.wait_group %0;\n" :: "n"(N));
}

__device__ __forceinline__ void mma_tf32(float c[4], uint32_t a0, uint32_t a1,
                                         uint32_t a2, uint32_t a3,
                                         uint32_t b0, uint32_t b1) {
    asm volatile(
        "mma.sync.aligned.m16n8k8.row.col.f32.tf32.tf32.f32 "
        "{%0,%1,%2,%3}, {%4,%5,%6,%7}, {%8,%9}, {%0,%1,%2,%3};\n"
        : "+f"(c[0]), "+f"(c[1]), "+f"(c[2]), "+f"(c[3])
        : "r"(a0), "r"(a1), "r"(a2), "r"(a3), "r"(b0), "r"(b1));
}

__global__ __launch_bounds__(256, 1) void gemm_kernel(const float* __restrict__ x,
                                                      const float* __restrict__ W,
                                                      const float* __restrict__ ka) {
    extern __shared__ float sm[];
    const int tid  = threadIdx.x;
    const int lane = tid & 31;
    const int warp = tid >> 5;
    const int wm = warp >> 2;
    const int wn = warp & 3;
    const int g   = lane >> 2;
    const int tig = lane & 3;
    const int row0 = blockIdx.x * BM;

    // staging coordinates (fixed per thread)
    const int xr = tid >> 3, xc = (tid & 7) << 2;       // +i*32 rows
    const int wr = tid >> 5, wc = (tid & 31) << 2;      // +i*8 rows

    auto stage = [&](int kc, int buf) {
        float* xb = sm + (buf ? OFF_X1 : OFF_X0);
        float* wb = sm + (buf ? OFF_W1 : OFF_W0);
#pragma unroll
        for (int i = 0; i < 4; i++) {
            int r = xr + i * 32;
            bool v = (row0 + r) < N_NODES;
            cp16(&xb[r * XS_STRIDE + xc],
                 &x[(row0 + r) * D_FEAT + kc * BK + xc], v);
        }
#pragma unroll
        for (int i = 0; i < 4; i++) {
            int r = wr + i * 8;
            cp16(&wb[r * WS_STRIDE + wc],
                 &W[(kc * BK + r) * D_FEAT + wc], true);
        }
        cp_commit();
    };

    float c[4][4][4];
#pragma unroll
    for (int mt = 0; mt < 4; mt++)
#pragma unroll
        for (int nt = 0; nt < 4; nt++)
#pragma unroll
            for (int r = 0; r < 4; r++) c[mt][nt][r] = 0.f;

    stage(0, 0);

#pragma unroll
    for (int kc = 0; kc < 4; ++kc) {
        if (kc < 3) stage(kc + 1, (kc + 1) & 1);
        if (kc < 3) cp_wait<1>(); else cp_wait<0>();
        __syncthreads();

        const float* xb = sm + ((kc & 1) ? OFF_X1 : OFF_X0);
        const float* wb = sm + ((kc & 1) ? OFF_W1 : OFF_W0);

#pragma unroll
        for (int ks = 0; ks < 4; ++ks) {
            const int k0 = ks * 8;
            uint32_t b[4][2];
#pragma unroll
            for (int nt = 0; nt < 4; nt++) {
                int n = wn * 32 + nt * 8 + g;
                b[nt][0] = f2tf(wb[(k0 + tig) * WS_STRIDE + n]);
                b[nt][1] = f2tf(wb[(k0 + tig + 4) * WS_STRIDE + n]);
            }
#pragma unroll
            for (int mt = 0; mt < 4; mt++) {
                int rb = wm * 64 + mt * 16;
                uint32_t a0 = f2tf(xb[(rb + g) * XS_STRIDE + k0 + tig]);
                uint32_t a1 = f2tf(xb[(rb + g + 8) * XS_STRIDE + k0 + tig]);
                uint32_t a2 = f2tf(xb[(rb + g) * XS_STRIDE + k0 + tig + 4]);
                uint32_t a3 = f2tf(xb[(rb + g + 8) * XS_STRIDE + k0 + tig + 4]);
#pragma unroll
                for (int nt = 0; nt < 4; nt++)
                    mma_tf32(c[mt][nt], a0, a1, a2, a3, b[nt][0], b[nt][1]);
            }
        }
        __syncthreads();
    }

    float2 wa1f[4], wa2f[4];
#pragma unroll
    for (int nt = 0; nt < 4; nt++) {
        int col = wn * 32 + nt * 8 + 2 * tig;
        wa1f[nt] = *(const float2*)&ka[col];
        wa2f[nt] = *(const float2*)&ka[D_FEAT + col];
    }

    float* sp1 = sm + OFF_SP1;   // [4][BM]
    float* sp2 = sm + OFF_SP2;

#pragma unroll
    for (int mt = 0; mt < 4; mt++) {
        float p1a = 0.f, p2a = 0.f;
        float p1b = 0.f, p2b = 0.f;
#pragma unroll
        for (int nt = 0; nt < 4; nt++) {
            int r0 = row0 + wm * 64 + mt * 16 + g;
            int col = wn * 32 + nt * 8 + 2 * tig;
            if (r0 < N_NODES)
                *(__half2*)&g_hh[r0 * D_FEAT + col] =
                    __floats2half2_rn(c[mt][nt][0], c[mt][nt][1]);
            if (r0 + 8 < N_NODES)
                *(__half2*)&g_hh[(r0 + 8) * D_FEAT + col] =
                    __floats2half2_rn(c[mt][nt][2], c[mt][nt][3]);
            p1a += c[mt][nt][0] * wa1f[nt].x + c[mt][nt][1] * wa1f[nt].y;
            p2a += c[mt][nt][0] * wa2f[nt].x + c[mt][nt][1] * wa2f[nt].y;
            p1b += c[mt][nt][2] * wa1f[nt].x + c[mt][nt][3] * wa1f[nt].y;
            p2b += c[mt][nt][2] * wa2f[nt].x + c[mt][nt][3] * wa2f[nt].y;
        }
#pragma unroll
        for (int o = 1; o <= 2; o <<= 1) {
            p1a += __shfl_xor_sync(0xffffffffu, p1a, o);
            p2a += __shfl_xor_sync(0xffffffffu, p2a, o);
            p1b += __shfl_xor_sync(0xffffffffu, p1b, o);
            p2b += __shfl_xor_sync(0xffffffffu, p2b, o);
        }
        if (tig == 0) {
            int rl = wm * 64 + mt * 16 + g;
            sp1[wn * BM + rl]     = p1a;  sp2[wn * BM + rl]     = p2a;
            sp1[wn * BM + rl + 8] = p1b;  sp2[wn * BM + rl + 8] = p2b;
        }
    }
    __syncthreads();
    if (tid < BM) {
        int grow = row0 + tid;
        if (grow < N_NODES) {
            g_s1[grow] = sp1[0 * BM + tid] + sp1[1 * BM + tid] +
                         sp1[2 * BM + tid] + sp1[3 * BM + tid];
            g_s2[grow] = sp2[0 * BM + tid] + sp2[1 * BM + tid] +
                         sp2[2 * BM + tid] + sp2[3 * BM + tid];
        }
    }
}

// ---------------------------------------------------------------------------
// edge: ONE pass over raw edges -> rowptr + compact dst + scores.
// Per-block inline dtype probe (first 512 odd words; L2-broadcast).
// ---------------------------------------------------------------------------
__global__ void edge_kernel(const int* __restrict__ ew) {
    __shared__ int nz;
    if (threadIdx.x == 0) nz = 0;
    __syncthreads();
    for (int i = threadIdx.x; i < 512; i += blockDim.x)
        if (ew[2 * i + 1] != 0) nz = 1;   // benign race, same value
    __syncthreads();
    const int stride = nz ? 2 : 4;        // nz -> int32 ; all-zero -> int64
    const int doff   = nz ? 1 : 2;

    int e = blockIdx.x * blockDim.x + threadIdx.x;
    if (e >= N_EDGES) return;
    int s = ew[e * stride];
    int d = ew[e * stride + doff];
    g_dst[e] = d;

    float l = g_s1[s] + g_s2[d];
    l = (l > 0.f) ? l : 0.2f * l;          // leaky_relu(0.2)
    l = fminf(fmaxf(l, -2.f), 2.f);        // clip
    g_w[e] = __expf(l);

    int sp = (e == 0) ? -1 : ew[(e - 1) * stride];
    for (int n = sp + 1; n <= s; ++n) g_rowptr[n] = e;
    if (e == N_EDGES - 1)
        for (int n = s + 1; n <= N_NODES; ++n) g_rowptr[n] = N_EDGES;
}

// ---------------------------------------------------------------------------
// agg: TWO nodes per warp, 16 lanes each; lane owns 8 cols (one uint4 row
// slice). Scores precomputed; dst compact. Unroll-4 for MLP against L2.
// ---------------------------------------------------------------------------
__device__ __forceinline__ void acc8(float4& a, float4& b, float w, uint4 r) {
    float2 f0 = __half22float2(*(__half2*)&r.x);
    float2 f1 = __half22float2(*(__half2*)&r.y);
    float2 f2 = __half22float2(*(__half2*)&r.z);
    float2 f3 = __half22float2(*(__half2*)&r.w);
    a.x += w * f0.x; a.y += w * f0.y; a.z += w * f1.x; a.w += w * f1.y;
    b.x += w * f2.x; b.y += w * f2.y; b.z += w * f3.x; b.w += w * f3.y;
}

__global__ void agg_kernel(float* __restrict__ out) {
    int t = blockIdx.x * blockDim.x + threadIdx.x;
    int warp = t >> 5, lane = t & 31;
    int hl = lane & 15;
    int node = (warp << 1) | (lane >> 4);
    if (node >= N_NODES) return;
    const int e0 = g_rowptr[node];
    const int e1 = g_rowptr[node + 1];
    const __half* __restrict__ hc = g_hh + hl * 8;

    float4 accA = make_float4(0.f, 0.f, 0.f, 0.f);
    float4 accB = make_float4(0.f, 0.f, 0.f, 0.f);
    float denom = 0.f;
    int e = e0;
    for (; e + 4 <= e1; e += 4) {
        int d0 = g_dst[e];
        int d1 = g_dst[e + 1];
        int d2 = g_dst[e + 2];
        int d3 = g_dst[e + 3];
        float w0 = g_w[e];
        float w1 = g_w[e + 1];
        float w2 = g_w[e + 2];
        float w3 = g_w[e + 3];
        uint4 r0 = *(const uint4*)&hc[d0 * D_FEAT];
        uint4 r1 = *(const uint4*)&hc[d1 * D_FEAT];
        uint4 r2 = *(const uint4*)&hc[d2 * D_FEAT];
        uint4 r3 = *(const uint4*)&hc[d3 * D_FEAT];
        denom += (w0 + w1) + (w2 + w3);
        acc8(accA, accB, w0, r0);
        acc8(accA, accB, w1, r1);
        acc8(accA, accB, w2, r2);
        acc8(accA, accB, w3, r3);
    }
    for (; e < e1; ++e) {
        int d = g_dst[e];
        float w = g_w[e];
        uint4 r = *(const uint4*)&hc[d * D_FEAT];
        denom += w;
        acc8(accA, accB, w, r);
    }
    float rinv = (e1 > e0) ? (1.0f / denom) : 0.f;
    accA.x *= rinv; accA.y *= rinv; accA.z *= rinv; accA.w *= rinv;
    accB.x *= rinv; accB.y *= rinv; accB.z *= rinv; accB.w *= rinv;
    float* o = out + node * D_FEAT + hl * 8;
    *(float4*)o       = accA;
    *(float4*)(o + 4) = accB;
}

// ---------------------------------------------------------------------------
extern "C" void kernel_launch(void* const* d_in, const int* in_sizes, int n_in,
                              void* d_out, int out_size) {
    // Identify inputs by element count (ordering-proof).
    const float* x  = nullptr;   // node_states: 6,400,000
    const void*  ed = nullptr;   // edges:       1,600,000
    const float* W  = nullptr;   // kernel:         16,384
    const float* ka = nullptr;   // kernel_attention:  256
    for (int i = 0; i < n_in; i++) {
        switch (in_sizes[i]) {
            case 6400000: x  = (const float*)d_in[i]; break;
            case 1600000: ed = d_in[i];               break;
            case 16384:   W  = (const float*)d_in[i]; break;
            case 256:     ka = (const float*)d_in[i]; break;
            default: break;
        }
    }
    float* out = (float*)d_out;  // [50000,128] float32

    cudaFuncSetAttribute(gemm_kernel,
                         cudaFuncAttributeMaxDynamicSharedMemorySize, SMEM_BYTES);
    gemm_kernel<<<(N_NODES + BM - 1) / BM, 256, SMEM_BYTES>>>(x, W, ka);
    edge_kernel<<<(N_EDGES + 255) / 256, 256>>>((const int*)ed);
    agg_kernel<<<(N_NODES * 16 + 255) / 256, 256>>>(out);
}

// round 16
// speedup vs baseline: 1.2574x; 1.0391x over previous
#include <cuda_runtime.h>
#include <cuda_fp16.h>
#include <cstdint>

#define N_NODES 50000
#define N_EDGES 800000
#define D_FEAT  128

// Scratch (device globals — no allocation allowed)
__device__ __half g_hh[N_NODES * D_FEAT];     // 12.8 MB, L2-resident
__device__ float g_s1[N_NODES];
__device__ float g_s2[N_NODES];
__device__ int   g_dst[N_EDGES];              // compact dst  3.2 MB
__device__ float g_w[N_EDGES];                // edge scores  3.2 MB
__device__ int   g_rowptr[N_NODES + 1];

// ---------------------------------------------------------------------------
// GEMM: h = X @ W via tf32 mma.sync.m16n8k8, cp.async double-buffered,
// 2 CTAs/SM (launch_bounds minBlocks=2 caps regs at 128 for latency hiding).
// Smem holds raw fp32; cvt.rna.tf32 applied at fragment-load time.
// Fused epilogue computes s1[row]=h·ka[0:128], s2[row]=h·ka[128:256].
// PTX ISA fragment layout m16n8k8 tf32 (g=lane>>2, tig=lane&3):
//   a0=(g,tig) a1=(g+8,tig) a2=(g,tig+4) a3=(g+8,tig+4)
//   b0=(k=tig,n=g) b1=(k=tig+4,n=g)
//   c0=(g,2tig) c1=(g,2tig+1) c2=(g+8,2tig) c3=(g+8,2tig+1)
// ---------------------------------------------------------------------------
#define BM 128
#define BK 32
#define XS_STRIDE 40    // A 32-bit LDS: banks 8g+tig all distinct
#define WS_STRIDE 136   // B 32-bit LDS: banks 8tig+g all distinct

// dynamic smem layout (floats)
#define XBUF_WORDS (BM * XS_STRIDE)           // 5120
#define WBUF_WORDS (BK * WS_STRIDE)           // 4352
#define OFF_X0 0
#define OFF_X1 (OFF_X0 + XBUF_WORDS)
#define OFF_W0 (OFF_X1 + XBUF_WORDS)
#define OFF_W1 (OFF_W0 + WBUF_WORDS)
#define OFF_SP1 (OFF_W1 + WBUF_WORDS)         // 4*BM
#define OFF_SP2 (OFF_SP1 + 4 * BM)
#define SMEM_WORDS (OFF_SP2 + 4 * BM)         // 19968
#define SMEM_BYTES (SMEM_WORDS * 4)           // 79872

__device__ __forceinline__ uint32_t f2tf(float f) {
    uint32_t r;
    asm("cvt.rna.tf32.f32 %0, %1;" : "=r"(r) : "f"(f));
    return r;
}

__device__ __forceinline__ void cp16(float* dst_smem, const float* src, bool valid) {
    uint32_t d = (uint32_t)__cvta_generic_to_shared(dst_smem);
    int sz = valid ? 16 : 0;
    asm volatile("cp.async.cg.shared.global [%0], [%1], 16, %2;\n"
                 :: "r"(d), "l"(src), "r"(sz));
}
__device__ __forceinline__ void cp_commit() {
    asm volatile("cp.async.commit_group;\n");
}
template <int N>
__device__ __forceinline__ void cp_wait() {
    asm volatile("cp.async.wait_group %0;\n" :: "n"(N));
}

__device__ __forceinline__ void mma_tf32(float c[4], uint32_t a0, uint32_t a1,
                                         uint32_t a2, uint32_t a3,
                                         uint32_t b0, uint32_t b1) {
    asm volatile(
        "mma.sync.aligned.m16n8k8.row.col.f32.tf32.tf32.f32 "
        "{%0,%1,%2,%3}, {%4,%5,%6,%7}, {%8,%9}, {%0,%1,%2,%3};\n"
        : "+f"(c[0]), "+f"(c[1]), "+f"(c[2]), "+f"(c[3])
        : "r"(a0), "r"(a1), "r"(a2), "r"(a3), "r"(b0), "r"(b1));
}

__global__ __launch_bounds__(256, 2) void gemm_kernel(const float* __restrict__ x,
                                                      const float* __restrict__ W,
                                                      const float* __restrict__ ka) {
    extern __shared__ float sm[];
    const int tid  = threadIdx.x;
    const int lane = tid & 31;
    const int warp = tid >> 5;
    const int wm = warp >> 2;
    const int wn = warp & 3;
    const int g   = lane >> 2;
    const int tig = lane & 3;
    const int row0 = blockIdx.x * BM;

    // staging coordinates (fixed per thread)
    const int xr = tid >> 3, xc = (tid & 7) << 2;       // +i*32 rows
    const int wr = tid >> 5, wc = (tid & 31) << 2;      // +i*8 rows

    auto stage = [&](int kc, int buf) {
        float* xb = sm + (buf ? OFF_X1 : OFF_X0);
        float* wb = sm + (buf ? OFF_W1 : OFF_W0);
#pragma unroll
        for (int i = 0; i < 4; i++) {
            int r = xr + i * 32;
            bool v = (row0 + r) < N_NODES;
            cp16(&xb[r * XS_STRIDE + xc],
                 &x[(row0 + r) * D_FEAT + kc * BK + xc], v);
        }
#pragma unroll
        for (int i = 0; i < 4; i++) {
            int r = wr + i * 8;
            cp16(&wb[r * WS_STRIDE + wc],
                 &W[(kc * BK + r) * D_FEAT + wc], true);
        }
        cp_commit();
    };

    float c[4][4][4];
#pragma unroll
    for (int mt = 0; mt < 4; mt++)
#pragma unroll
        for (int nt = 0; nt < 4; nt++)
#pragma unroll
            for (int r = 0; r < 4; r++) c[mt][nt][r] = 0.f;

    stage(0, 0);

#pragma unroll
    for (int kc = 0; kc < 4; ++kc) {
        if (kc < 3) stage(kc + 1, (kc + 1) & 1);
        if (kc < 3) cp_wait<1>(); else cp_wait<0>();
        __syncthreads();

        const float* xb = sm + ((kc & 1) ? OFF_X1 : OFF_X0);
        const float* wb = sm + ((kc & 1) ? OFF_W1 : OFF_W0);

#pragma unroll
        for (int ks = 0; ks < 4; ++ks) {
            const int k0 = ks * 8;
            uint32_t b[4][2];
#pragma unroll
            for (int nt = 0; nt < 4; nt++) {
                int n = wn * 32 + nt * 8 + g;
                b[nt][0] = f2tf(wb[(k0 + tig) * WS_STRIDE + n]);
                b[nt][1] = f2tf(wb[(k0 + tig + 4) * WS_STRIDE + n]);
            }
#pragma unroll
            for (int mt = 0; mt < 4; mt++) {
                int rb = wm * 64 + mt * 16;
                uint32_t a0 = f2tf(xb[(rb + g) * XS_STRIDE + k0 + tig]);
                uint32_t a1 = f2tf(xb[(rb + g + 8) * XS_STRIDE + k0 + tig]);
                uint32_t a2 = f2tf(xb[(rb + g) * XS_STRIDE + k0 + tig + 4]);
                uint32_t a3 = f2tf(xb[(rb + g + 8) * XS_STRIDE + k0 + tig + 4]);
#pragma unroll
                for (int nt = 0; nt < 4; nt++)
                    mma_tf32(c[mt][nt], a0, a1, a2, a3, b[nt][0], b[nt][1]);
            }
        }
        __syncthreads();
    }

    float2 wa1f[4], wa2f[4];
#pragma unroll
    for (int nt = 0; nt < 4; nt++) {
        int col = wn * 32 + nt * 8 + 2 * tig;
        wa1f[nt] = *(const float2*)&ka[col];
        wa2f[nt] = *(const float2*)&ka[D_FEAT + col];
    }

    float* sp1 = sm + OFF_SP1;   // [4][BM]
    float* sp2 = sm + OFF_SP2;

#pragma unroll
    for (int mt = 0; mt < 4; mt++) {
        float p1a = 0.f, p2a = 0.f;
        float p1b = 0.f, p2b = 0.f;
#pragma unroll
        for (int nt = 0; nt < 4; nt++) {
            int r0 = row0 + wm * 64 + mt * 16 + g;
            int col = wn * 32 + nt * 8 + 2 * tig;
            if (r0 < N_NODES)
                *(__half2*)&g_hh[r0 * D_FEAT + col] =
                    __floats2half2_rn(c[mt][nt][0], c[mt][nt][1]);
            if (r0 + 8 < N_NODES)
                *(__half2*)&g_hh[(r0 + 8) * D_FEAT + col] =
                    __floats2half2_rn(c[mt][nt][2], c[mt][nt][3]);
            p1a += c[mt][nt][0] * wa1f[nt].x + c[mt][nt][1] * wa1f[nt].y;
            p2a += c[mt][nt][0] * wa2f[nt].x + c[mt][nt][1] * wa2f[nt].y;
            p1b += c[mt][nt][2] * wa1f[nt].x + c[mt][nt][3] * wa1f[nt].y;
            p2b += c[mt][nt][2] * wa2f[nt].x + c[mt][nt][3] * wa2f[nt].y;
        }
#pragma unroll
        for (int o = 1; o <= 2; o <<= 1) {
            p1a += __shfl_xor_sync(0xffffffffu, p1a, o);
            p2a += __shfl_xor_sync(0xffffffffu, p2a, o);
            p1b += __shfl_xor_sync(0xffffffffu, p1b, o);
            p2b += __shfl_xor_sync(0xffffffffu, p2b, o);
        }
        if (tig == 0) {
            int rl = wm * 64 + mt * 16 + g;
            sp1[wn * BM + rl]     = p1a;  sp2[wn * BM + rl]     = p2a;
            sp1[wn * BM + rl + 8] = p1b;  sp2[wn * BM + rl + 8] = p2b;
        }
    }
    __syncthreads();
    if (tid < BM) {
        int grow = row0 + tid;
        if (grow < N_NODES) {
            g_s1[grow] = sp1[0 * BM + tid] + sp1[1 * BM + tid] +
                         sp1[2 * BM + tid] + sp1[3 * BM + tid];
            g_s2[grow] = sp2[0 * BM + tid] + sp2[1 * BM + tid] +
                         sp2[2 * BM + tid] + sp2[3 * BM + tid];
        }
    }
}

// ---------------------------------------------------------------------------
// edge: ONE pass over raw edges -> rowptr + compact dst + scores.
// Per-block inline dtype probe (first 512 odd words; L2-broadcast).
// ---------------------------------------------------------------------------
__global__ void edge_kernel(const int* __restrict__ ew) {
    __shared__ int nz;
    if (threadIdx.x == 0) nz = 0;
    __syncthreads();
    for (int i = threadIdx.x; i < 512; i += blockDim.x)
        if (ew[2 * i + 1] != 0) nz = 1;   // benign race, same value
    __syncthreads();
    const int stride = nz ? 2 : 4;        // nz -> int32 ; all-zero -> int64
    const int doff   = nz ? 1 : 2;

    int e = blockIdx.x * blockDim.x + threadIdx.x;
    if (e >= N_EDGES) return;
    int s = ew[e * stride];
    int d = ew[e * stride + doff];
    g_dst[e] = d;

    float l = g_s1[s] + g_s2[d];
    l = (l > 0.f) ? l : 0.2f * l;          // leaky_relu(0.2)
    l = fminf(fmaxf(l, -2.f), 2.f);        // clip
    g_w[e] = __expf(l);

    int sp = (e == 0) ? -1 : ew[(e - 1) * stride];
    for (int n = sp + 1; n <= s; ++n) g_rowptr[n] = e;
    if (e == N_EDGES - 1)
        for (int n = s + 1; n <= N_NODES; ++n) g_rowptr[n] = N_EDGES;
}

// ---------------------------------------------------------------------------
// agg: TWO nodes per warp, 16 lanes each; lane owns 8 cols (one uint4 row
// slice). Scores precomputed; dst compact. Unroll-4 for MLP against L2.
// ---------------------------------------------------------------------------
__device__ __forceinline__ void acc8(float4& a, float4& b, float w, uint4 r) {
    float2 f0 = __half22float2(*(__half2*)&r.x);
    float2 f1 = __half22float2(*(__half2*)&r.y);
    float2 f2 = __half22float2(*(__half2*)&r.z);
    float2 f3 = __half22float2(*(__half2*)&r.w);
    a.x += w * f0.x; a.y += w * f0.y; a.z += w * f1.x; a.w += w * f1.y;
    b.x += w * f2.x; b.y += w * f2.y; b.z += w * f3.x; b.w += w * f3.y;
}

__global__ void agg_kernel(float* __restrict__ out) {
    int t = blockIdx.x * blockDim.x + threadIdx.x;
    int warp = t >> 5, lane = t & 31;
    int hl = lane & 15;
    int node = (warp << 1) | (lane >> 4);
    if (node >= N_NODES) return;
    const int e0 = g_rowptr[node];
    const int e1 = g_rowptr[node + 1];
    const __half* __restrict__ hc = g_hh + hl * 8;

    float4 accA = make_float4(0.f, 0.f, 0.f, 0.f);
    float4 accB = make_float4(0.f, 0.f, 0.f, 0.f);
    float denom = 0.f;
    int e = e0;
    for (; e + 4 <= e1; e += 4) {
        int d0 = g_dst[e];
        int d1 = g_dst[e + 1];
        int d2 = g_dst[e + 2];
        int d3 = g_dst[e + 3];
        float w0 = g_w[e];
        float w1 = g_w[e + 1];
        float w2 = g_w[e + 2];
        float w3 = g_w[e + 3];
        uint4 r0 = *(const uint4*)&hc[d0 * D_FEAT];
        uint4 r1 = *(const uint4*)&hc[d1 * D_FEAT];
        uint4 r2 = *(const uint4*)&hc[d2 * D_FEAT];
        uint4 r3 = *(const uint4*)&hc[d3 * D_FEAT];
        denom += (w0 + w1) + (w2 + w3);
        acc8(accA, accB, w0, r0);
        acc8(accA, accB, w1, r1);
        acc8(accA, accB, w2, r2);
        acc8(accA, accB, w3, r3);
    }
    for (; e < e1; ++e) {
        int d = g_dst[e];
        float w = g_w[e];
        uint4 r = *(const uint4*)&hc[d * D_FEAT];
        denom += w;
        acc8(accA, accB, w, r);
    }
    float rinv = (e1 > e0) ? (1.0f / denom) : 0.f;
    accA.x *= rinv; accA.y *= rinv; accA.z *= rinv; accA.w *= rinv;
    accB.x *= rinv; accB.y *= rinv; accB.z *= rinv; accB.w *= rinv;
    float* o = out + node * D_FEAT + hl * 8;
    *(float4*)o       = accA;
    *(float4*)(o + 4) = accB;
}

// ---------------------------------------------------------------------------
extern "C" void kernel_launch(void* const* d_in, const int* in_sizes, int n_in,
                              void* d_out, int out_size) {
    // Identify inputs by element count (ordering-proof).
    const float* x  = nullptr;   // node_states: 6,400,000
    const void*  ed = nullptr;   // edges:       1,600,000
    const float* W  = nullptr;   // kernel:         16,384
    const float* ka = nullptr;   // kernel_attention:  256
    for (int i = 0; i < n_in; i++) {
        switch (in_sizes[i]) {
            case 6400000: x  = (const float*)d_in[i]; break;
            case 1600000: ed = d_in[i];               break;
            case 16384:   W  = (const float*)d_in[i]; break;
            case 256:     ka = (const float*)d_in[i]; break;
            default: break;
        }
    }
    float* out = (float*)d_out;  // [50000,128] float32

    cudaFuncSetAttribute(gemm_kernel,
                         cudaFuncAttributeMaxDynamicSharedMemorySize, SMEM_BYTES);
    gemm_kernel<<<(N_NODES + BM - 1) / BM, 256, SMEM_BYTES>>>(x, W, ka);
    edge_kernel<<<(N_EDGES + 255) / 256, 256>>>((const int*)ed);
    agg_kernel<<<(N_NODES * 16 + 255) / 256, 256>>>(out);
}